// round 1
// baseline (speedup 1.0000x reference)
#include <cuda_runtime.h>

#define NR0 4096
#define NR1 8192
#define NR2 4096
#define NT  16384     // NR0+NR1+NR2
#define C   64
#define OUTC 32
#define NB  64        // batch (number of complexes)

// ---- scratch (device globals; no allocation allowed) ----
__device__ float g_dinv[NT];
__device__ float g_z  [NT * C];
__device__ float g_xA [NT * C];
__device__ float g_xB [NT * C];
__device__ float g_pooled[3 * NB * C];

// ============================================================
// dinv[i] = rsqrt(rowsum |L_i|), 0 if rowsum == 0
// one block per global row (rank decoded from row index)
// ============================================================
__global__ void dinv_kernel(const float* __restrict__ L0,
                            const float* __restrict__ L1,
                            const float* __restrict__ L2) {
    int grow = blockIdx.x;
    const float* L; int N; int lr;
    if (grow < NR0)             { L = L0; N = NR0; lr = grow; }
    else if (grow < NR0 + NR1)  { L = L1; N = NR1; lr = grow - NR0; }
    else                        { L = L2; N = NR2; lr = grow - NR0 - NR1; }

    const float4* row = (const float4*)(L + (size_t)lr * N);
    int n4 = N >> 2;
    float s = 0.f;
    for (int j = threadIdx.x; j < n4; j += blockDim.x) {
        float4 v = row[j];
        s += fabsf(v.x) + fabsf(v.y) + fabsf(v.z) + fabsf(v.w);
    }
    __shared__ float red[4];
    for (int o = 16; o > 0; o >>= 1) s += __shfl_down_sync(0xffffffffu, s, o);
    if ((threadIdx.x & 31) == 0) red[threadIdx.x >> 5] = s;
    __syncthreads();
    if (threadIdx.x == 0) {
        float d = red[0] + red[1] + red[2] + red[3];
        g_dinv[grow] = (d != 0.f) ? rsqrtf(d) : 0.f;
    }
}

// ============================================================
// z = dinv .* (x @ W[layer])   (32 rows per block, 256 thr)
// ============================================================
__global__ __launch_bounds__(256) void xw_kernel(
    const float* __restrict__ x0, const float* __restrict__ x1,
    const float* __restrict__ x2,
    const float* __restrict__ W0, const float* __restrict__ W1,
    const float* __restrict__ W2, int layer)
{
    __shared__ float Ws[C * C];
    __shared__ float xs[32 * C];

    int growBase = blockIdx.x * 32;
    const float* W; const float* xsrc;
    if (growBase < NR0) {
        W = W0;
        xsrc = layer ? (g_xA + (size_t)growBase * C) : (x0 + (size_t)growBase * C);
    } else if (growBase < NR0 + NR1) {
        W = W1;
        xsrc = layer ? (g_xA + (size_t)growBase * C) : (x1 + (size_t)(growBase - NR0) * C);
    } else {
        W = W2;
        xsrc = layer ? (g_xA + (size_t)growBase * C) : (x2 + (size_t)(growBase - NR0 - NR1) * C);
    }
    W += layer * C * C;

    int tid = threadIdx.x;
    for (int i = tid; i < C * C; i += 256) Ws[i] = W[i];
    for (int i = tid; i < 32 * C; i += 256) xs[i] = xsrc[i];
    __syncthreads();

    int c = tid & 63, rb = tid >> 6;
    #pragma unroll
    for (int rq = 0; rq < 8; rq++) {
        int r = rb * 8 + rq;
        float acc = 0.f;
        #pragma unroll
        for (int k = 0; k < C; k++) acc += xs[r * C + k] * Ws[k * C + c];
        int grow = growBase + r;
        g_z[(size_t)grow * C + c] = acc * g_dinv[grow];
    }
}

// ============================================================
// dst = relu(dinv .* (L @ z))    the hot GEMM
// BM=64, BN=64(=C), BK=32, 256 threads, 4x4 micro-tile
// one launch covers all ranks: blocks [0,64)=r0 [64,192)=r1 [192,256)=r2
// ============================================================
__global__ __launch_bounds__(256) void gemm_kernel(
    const float* __restrict__ L0, const float* __restrict__ L1,
    const float* __restrict__ L2, int layer)
{
    __shared__ float As[64][36];   // padded: conflict-free
    __shared__ float Bs[32][C];

    int bx = blockIdx.x;
    const float* L; int N; int lrowBase; int growBase;
    if (bx < 64)       { L = L0; N = NR0; lrowBase = bx * 64;        growBase = lrowBase; }
    else if (bx < 192) { L = L1; N = NR1; lrowBase = (bx - 64) * 64; growBase = NR0 + lrowBase; }
    else               { L = L2; N = NR2; lrowBase = (bx - 192) * 64; growBase = NR0 + NR1 + lrowBase; }
    int zRankOff = growBase - lrowBase;
    float* dst = layer ? g_xB : g_xA;

    int tid = threadIdx.x;
    int tx = tid & 15;       // 0..15 -> cols tx*4
    int ty = tid >> 4;       // 0..15 -> rows ty*4

    float acc[4][4];
    #pragma unroll
    for (int i = 0; i < 4; i++)
        #pragma unroll
        for (int j = 0; j < 4; j++) acc[i][j] = 0.f;

    for (int k0 = 0; k0 < N; k0 += 32) {
        // load A tile: 64x32 floats = 512 float4, 2 per thread
        #pragma unroll
        for (int q = 0; q < 2; q++) {
            int idx = tid + q * 256;
            int r  = idx >> 3;
            int k4 = idx & 7;
            float4 v = *(const float4*)&L[(size_t)(lrowBase + r) * N + k0 + k4 * 4];
            *(float4*)&As[r][k4 * 4] = v;
        }
        // load B tile: 32x64 = 512 float4, 2 per thread
        #pragma unroll
        for (int q = 0; q < 2; q++) {
            int idx = tid + q * 256;
            int r  = idx >> 4;
            int c4 = idx & 15;
            *(float4*)&Bs[r][c4 * 4] =
                *(const float4*)&g_z[(size_t)(zRankOff + k0 + r) * C + c4 * 4];
        }
        __syncthreads();

        #pragma unroll
        for (int kk = 0; kk < 32; kk++) {
            float a0 = As[ty * 4 + 0][kk];
            float a1 = As[ty * 4 + 1][kk];
            float a2 = As[ty * 4 + 2][kk];
            float a3 = As[ty * 4 + 3][kk];
            float4 b = *(float4*)&Bs[kk][tx * 4];
            acc[0][0] += a0 * b.x; acc[0][1] += a0 * b.y; acc[0][2] += a0 * b.z; acc[0][3] += a0 * b.w;
            acc[1][0] += a1 * b.x; acc[1][1] += a1 * b.y; acc[1][2] += a1 * b.z; acc[1][3] += a1 * b.w;
            acc[2][0] += a2 * b.x; acc[2][1] += a2 * b.y; acc[2][2] += a2 * b.z; acc[2][3] += a2 * b.w;
            acc[3][0] += a3 * b.x; acc[3][1] += a3 * b.y; acc[3][2] += a3 * b.z; acc[3][3] += a3 * b.w;
        }
        __syncthreads();
    }

    // epilogue: scale by dinv_row, relu, store
    #pragma unroll
    for (int i = 0; i < 4; i++) {
        int grow = growBase + ty * 4 + i;
        float dv = g_dinv[grow];
        float4 o;
        o.x = fmaxf(acc[i][0] * dv, 0.f);
        o.y = fmaxf(acc[i][1] * dv, 0.f);
        o.z = fmaxf(acc[i][2] * dv, 0.f);
        o.w = fmaxf(acc[i][3] * dv, 0.f);
        *(float4*)&dst[(size_t)grow * C + tx * 4] = o;
    }
}

// ============================================================
// readout
// ============================================================
__global__ void zero_pooled_kernel() {
    int i = blockIdx.x * blockDim.x + threadIdx.x;
    if (i < 3 * NB * C) g_pooled[i] = 0.f;
}

__global__ void pool_kernel(const int* __restrict__ bel0,
                            const int* __restrict__ bel1,
                            const int* __restrict__ bel2) {
    int grow = blockIdx.x;
    int rank, lr;
    if (grow < NR0)            { rank = 0; lr = grow; }
    else if (grow < NR0 + NR1) { rank = 1; lr = grow - NR0; }
    else                       { rank = 2; lr = grow - NR0 - NR1; }
    const int* bel = (rank == 0) ? bel0 : (rank == 1 ? bel1 : bel2);
    int b = bel[lr];
    float v = g_xB[(size_t)grow * C + threadIdx.x];
    atomicAdd(&g_pooled[rank * NB * C + b * C + threadIdx.x], v);
}

__global__ void out_kernel(const float* __restrict__ Wr0, const float* __restrict__ br0,
                           const float* __restrict__ Wr1, const float* __restrict__ br1,
                           const float* __restrict__ Wr2, const float* __restrict__ br2,
                           float* __restrict__ out) {
    int b = blockIdx.x;      // 0..63
    int o = threadIdx.x;     // 0..31
    float acc = br0[o] + br1[o] + br2[o];
    const float* Wrs[3] = {Wr0, Wr1, Wr2};
    #pragma unroll
    for (int r = 0; r < 3; r++) {
        const float* Wr = Wrs[r];
        const float* p  = &g_pooled[r * NB * C + b * C];
        #pragma unroll 8
        for (int c = 0; c < C; c++) acc += p[c] * Wr[c * OUTC + o];
    }
    out[b * OUTC + o] = acc;
}

// ============================================================
extern "C" void kernel_launch(void* const* d_in, const int* in_sizes, int n_in,
                              void* d_out, int out_size) {
    const float* x0  = (const float*)d_in[0];
    const float* x1  = (const float*)d_in[1];
    const float* x2  = (const float*)d_in[2];
    const float* L0  = (const float*)d_in[3];
    const float* L1  = (const float*)d_in[4];
    const float* L2  = (const float*)d_in[5];
    const int*   bel0 = (const int*)d_in[6];
    const int*   bel1 = (const int*)d_in[7];
    const int*   bel2 = (const int*)d_in[8];
    const float* W0  = (const float*)d_in[9];
    const float* W1  = (const float*)d_in[10];
    const float* W2  = (const float*)d_in[11];
    const float* Wr0 = (const float*)d_in[12];
    const float* br0 = (const float*)d_in[13];
    const float* Wr1 = (const float*)d_in[14];
    const float* br1 = (const float*)d_in[15];
    const float* Wr2 = (const float*)d_in[16];
    const float* br2 = (const float*)d_in[17];

    dinv_kernel<<<NT, 128>>>(L0, L1, L2);

    for (int layer = 0; layer < 2; layer++) {
        xw_kernel<<<NT / 32, 256>>>(x0, x1, x2, W0, W1, W2, layer);
        gemm_kernel<<<256, 256>>>(L0, L1, L2, layer);
    }

    zero_pooled_kernel<<<(3 * NB * C + 255) / 256, 256>>>();
    pool_kernel<<<NT, 64>>>(bel0, bel1, bel2);
    out_kernel<<<NB, OUTC>>>(Wr0, br0, Wr1, br1, Wr2, br2, (float*)d_out);
}

// round 3
// speedup vs baseline: 1.8768x; 1.8768x over previous
#include <cuda_runtime.h>
#include <cstdint>

#define NR0 4096
#define NR1 8192
#define NR2 4096
#define NT  16384     // NR0+NR1+NR2
#define C   64
#define OUTC 32
#define NB  64

// ---- scratch (device globals; no allocation allowed) ----
__device__ float g_dinv[NT];
__device__ float g_zT[C * NT];        // z transposed [C][NT] (B operand, K-major, full fp32)
__device__ float g_xA[NT * C];
__device__ float g_xB[NT * C];
__device__ float g_pooled[3 * NB * C];

// ============================================================
// helpers
// ============================================================
__device__ __forceinline__ uint32_t pack_bf16(float lo, float hi) {
    // result: [15:0] = bf16(lo), [31:16] = bf16(hi)
    uint32_t r;
    asm("cvt.rn.bf16x2.f32 %0, %1, %2;" : "=r"(r) : "f"(hi), "f"(lo));
    return r;
}

__device__ __forceinline__ void mma_bf16(float* c, const uint32_t* a, const uint32_t* b) {
    asm volatile("mma.sync.aligned.m16n8k16.row.col.f32.bf16.bf16.f32 "
        "{%0,%1,%2,%3}, {%4,%5,%6,%7}, {%8,%9}, {%0,%1,%2,%3};"
        : "+f"(c[0]), "+f"(c[1]), "+f"(c[2]), "+f"(c[3])
        : "r"(a[0]), "r"(a[1]), "r"(a[2]), "r"(a[3]), "r"(b[0]), "r"(b[1]));
}

// ============================================================
// dinv[i] = rsqrt(rowsum |L_i|), 0 if rowsum == 0
// ============================================================
__global__ void dinv_kernel(const float* __restrict__ L0,
                            const float* __restrict__ L1,
                            const float* __restrict__ L2) {
    int grow = blockIdx.x;
    const float* L; int N; int lr;
    if (grow < NR0)             { L = L0; N = NR0; lr = grow; }
    else if (grow < NR0 + NR1)  { L = L1; N = NR1; lr = grow - NR0; }
    else                        { L = L2; N = NR2; lr = grow - NR0 - NR1; }

    const float4* row = (const float4*)(L + (size_t)lr * N);
    int n4 = N >> 2;
    float s = 0.f;
    for (int j = threadIdx.x; j < n4; j += blockDim.x) {
        float4 v = row[j];
        s += fabsf(v.x) + fabsf(v.y) + fabsf(v.z) + fabsf(v.w);
    }
    __shared__ float red[4];
    for (int o = 16; o > 0; o >>= 1) s += __shfl_down_sync(0xffffffffu, s, o);
    if ((threadIdx.x & 31) == 0) red[threadIdx.x >> 5] = s;
    __syncthreads();
    if (threadIdx.x == 0) {
        float d = red[0] + red[1] + red[2] + red[3];
        g_dinv[grow] = (d != 0.f) ? rsqrtf(d) : 0.f;
    }
}

// ============================================================
// zT[c][row] = dinv[row] * (x @ W[layer])[row][c]   (fp32)
// ============================================================
__global__ __launch_bounds__(256) void xw_kernel(
    const float* __restrict__ x0, const float* __restrict__ x1,
    const float* __restrict__ x2,
    const float* __restrict__ W0, const float* __restrict__ W1,
    const float* __restrict__ W2, int layer)
{
    __shared__ float Ws[C * C];
    __shared__ float xs[32 * C];
    __shared__ float zs[32][C + 1];

    int growBase = blockIdx.x * 32;
    const float* W; const float* xsrc;
    if (growBase < NR0) {
        W = W0;
        xsrc = layer ? (g_xA + (size_t)growBase * C) : (x0 + (size_t)growBase * C);
    } else if (growBase < NR0 + NR1) {
        W = W1;
        xsrc = layer ? (g_xA + (size_t)growBase * C) : (x1 + (size_t)(growBase - NR0) * C);
    } else {
        W = W2;
        xsrc = layer ? (g_xA + (size_t)growBase * C) : (x2 + (size_t)(growBase - NR0 - NR1) * C);
    }
    W += layer * C * C;

    int tid = threadIdx.x;
    for (int i = tid; i < C * C; i += 256) Ws[i] = W[i];
    for (int i = tid; i < 32 * C; i += 256) xs[i] = xsrc[i];
    __syncthreads();

    int c = tid & 63, rb = tid >> 6;
    #pragma unroll
    for (int rq = 0; rq < 8; rq++) {
        int r = rb * 8 + rq;
        float acc = 0.f;
        #pragma unroll
        for (int k = 0; k < C; k++) acc += xs[r * C + k] * Ws[k * C + c];
        zs[r][c] = acc * g_dinv[growBase + r];
    }
    __syncthreads();

    int c2 = tid >> 2, seg = tid & 3;
    float* o = g_zT + (size_t)c2 * NT + growBase + seg * 8;
    #pragma unroll
    for (int j = 0; j < 8; j++) o[j] = zs[seg * 8 + j][c2];
}

// ============================================================
// mma.sync bf16x3 GEMM:  dst = relu(dinv .* (L @ z))
// BM=128, BN=64, BK=32. 256 threads = 8 warps (4m x 2n), m32n32 per warp.
// fp32 operands split into bf16 hi/lo; D += AhBh + AhBl + AlBh (fp32 acc).
// ============================================================
#define SA 40   // smem row pitch (halves) for A tiles
#define SB 40   // smem row pitch (halves) for B tiles

__global__ __launch_bounds__(256) void gemm_mma(
    const float* __restrict__ L0, const float* __restrict__ L1,
    const float* __restrict__ L2, int layer)
{
    __shared__ __align__(16) uint16_t Ahi[128 * SA];
    __shared__ __align__(16) uint16_t Alo[128 * SA];
    __shared__ __align__(16) uint16_t Bhi[C * SB];
    __shared__ __align__(16) uint16_t Blo[C * SB];

    int bx = blockIdx.x;
    const float* L; int N, lrowBase, growBase;
    if (bx < 32)      { L = L0; N = NR0; lrowBase = bx * 128;        growBase = lrowBase; }
    else if (bx < 96) { L = L1; N = NR1; lrowBase = (bx - 32) * 128; growBase = NR0 + lrowBase; }
    else              { L = L2; N = NR2; lrowBase = (bx - 96) * 128; growBase = NR0 + NR1 + lrowBase; }
    int zOff = growBase - lrowBase;
    int nc = N / 32;
    float* dst = layer ? g_xB : g_xA;

    int tid = threadIdx.x;
    int wid = tid >> 5, lane = tid & 31;
    int g = lane >> 2, tg = lane & 3;
    int wm = wid >> 1, wn = wid & 1;

    // ---- loader setup: A 1024 float4 (4/thread), B 512 float4 (2/thread) ----
    const float* aPtr[4]; int aRow[4], aK4[4];
    #pragma unroll
    for (int q = 0; q < 4; q++) {
        int idx = q * 256 + tid;
        aRow[q] = idx >> 3; aK4[q] = idx & 7;
        aPtr[q] = L + (size_t)(lrowBase + aRow[q]) * N + aK4[q] * 4;
    }
    const float* bPtr[2]; int bRow[2], bK4[2];
    #pragma unroll
    for (int q = 0; q < 2; q++) {
        int idx = q * 256 + tid;
        bRow[q] = idx >> 3; bK4[q] = idx & 7;
        bPtr[q] = g_zT + (size_t)bRow[q] * NT + zOff + bK4[q] * 4;
    }

    float acc[2][4][4];
    #pragma unroll
    for (int mt = 0; mt < 2; mt++)
        #pragma unroll
        for (int nt = 0; nt < 4; nt++)
            #pragma unroll
            for (int i = 0; i < 4; i++) acc[mt][nt][i] = 0.f;

    float4 ra[4], rb[2];
    #pragma unroll
    for (int q = 0; q < 4; q++) ra[q] = *(const float4*)(aPtr[q]);
    #pragma unroll
    for (int q = 0; q < 2; q++) rb[q] = *(const float4*)(bPtr[q]);

    for (int cI = 0; cI < nc; cI++) {
        __syncthreads();    // previous compute done; smem safe to overwrite

        // convert + store current chunk
        #pragma unroll
        for (int q = 0; q < 4; q++) {
            float4 v = ra[q];
            uint32_t h0 = pack_bf16(v.x, v.y);
            uint32_t h1 = pack_bf16(v.z, v.w);
            float r0 = v.x - __uint_as_float(h0 << 16);
            float r1 = v.y - __uint_as_float(h0 & 0xFFFF0000u);
            float r2 = v.z - __uint_as_float(h1 << 16);
            float r3 = v.w - __uint_as_float(h1 & 0xFFFF0000u);
            uint32_t l0 = pack_bf16(r0, r1);
            uint32_t l1 = pack_bf16(r2, r3);
            int off = aRow[q] * SA + aK4[q] * 4;
            *(uint2*)&Ahi[off] = make_uint2(h0, h1);
            *(uint2*)&Alo[off] = make_uint2(l0, l1);
        }
        #pragma unroll
        for (int q = 0; q < 2; q++) {
            float4 v = rb[q];
            uint32_t h0 = pack_bf16(v.x, v.y);
            uint32_t h1 = pack_bf16(v.z, v.w);
            float r0 = v.x - __uint_as_float(h0 << 16);
            float r1 = v.y - __uint_as_float(h0 & 0xFFFF0000u);
            float r2 = v.z - __uint_as_float(h1 << 16);
            float r3 = v.w - __uint_as_float(h1 & 0xFFFF0000u);
            uint32_t l0 = pack_bf16(r0, r1);
            uint32_t l1 = pack_bf16(r2, r3);
            int off = bRow[q] * SB + bK4[q] * 4;
            *(uint2*)&Bhi[off] = make_uint2(h0, h1);
            *(uint2*)&Blo[off] = make_uint2(l0, l1);
        }
        __syncthreads();

        // issue next chunk's global loads (hide latency under mma)
        if (cI + 1 < nc) {
            int k0 = (cI + 1) * 32;
            #pragma unroll
            for (int q = 0; q < 4; q++) ra[q] = *(const float4*)(aPtr[q] + k0);
            #pragma unroll
            for (int q = 0; q < 2; q++) rb[q] = *(const float4*)(bPtr[q] + k0);
        }

        // compute: 2 k16-steps
        #pragma unroll
        for (int ks = 0; ks < 2; ks++) {
            uint32_t ah[2][4], al[2][4];
            #pragma unroll
            for (int mt = 0; mt < 2; mt++) {
                int r0 = (wm * 32 + mt * 16 + g) * SA + ks * 16 + tg * 2;
                ah[mt][0] = *(const uint32_t*)&Ahi[r0];
                ah[mt][1] = *(const uint32_t*)&Ahi[r0 + 8 * SA];
                ah[mt][2] = *(const uint32_t*)&Ahi[r0 + 8];
                ah[mt][3] = *(const uint32_t*)&Ahi[r0 + 8 * SA + 8];
                al[mt][0] = *(const uint32_t*)&Alo[r0];
                al[mt][1] = *(const uint32_t*)&Alo[r0 + 8 * SA];
                al[mt][2] = *(const uint32_t*)&Alo[r0 + 8];
                al[mt][3] = *(const uint32_t*)&Alo[r0 + 8 * SA + 8];
            }
            uint32_t bh[4][2], bl[4][2];
            #pragma unroll
            for (int nt = 0; nt < 4; nt++) {
                int b0 = (wn * 32 + nt * 8 + g) * SB + ks * 16 + tg * 2;
                bh[nt][0] = *(const uint32_t*)&Bhi[b0];
                bh[nt][1] = *(const uint32_t*)&Bhi[b0 + 8];
                bl[nt][0] = *(const uint32_t*)&Blo[b0];
                bl[nt][1] = *(const uint32_t*)&Blo[b0 + 8];
            }
            #pragma unroll
            for (int mt = 0; mt < 2; mt++)
                #pragma unroll
                for (int nt = 0; nt < 4; nt++) {
                    mma_bf16(acc[mt][nt], ah[mt], bh[nt]);
                    mma_bf16(acc[mt][nt], ah[mt], bl[nt]);
                    mma_bf16(acc[mt][nt], al[mt], bh[nt]);
                }
        }
    }

    // ---- epilogue: dinv row-scale + relu, write fp32 ----
    #pragma unroll
    for (int mt = 0; mt < 2; mt++) {
        int row0 = wm * 32 + mt * 16 + g;
        float dv0 = g_dinv[growBase + row0];
        float dv1 = g_dinv[growBase + row0 + 8];
        #pragma unroll
        for (int nt = 0; nt < 4; nt++) {
            int col = wn * 32 + nt * 8 + tg * 2;
            float* c = acc[mt][nt];
            float2 o0, o1;
            o0.x = fmaxf(c[0] * dv0, 0.f);
            o0.y = fmaxf(c[1] * dv0, 0.f);
            o1.x = fmaxf(c[2] * dv1, 0.f);
            o1.y = fmaxf(c[3] * dv1, 0.f);
            *(float2*)&dst[(size_t)(growBase + row0) * C + col]     = o0;
            *(float2*)&dst[(size_t)(growBase + row0 + 8) * C + col] = o1;
        }
    }
}

// ============================================================
// readout
// ============================================================
__global__ void zero_pooled_kernel() {
    int i = blockIdx.x * blockDim.x + threadIdx.x;
    if (i < 3 * NB * C) g_pooled[i] = 0.f;
}

__global__ void pool_kernel(const int* __restrict__ bel0,
                            const int* __restrict__ bel1,
                            const int* __restrict__ bel2) {
    int grow = blockIdx.x;
    int rank, lr;
    if (grow < NR0)            { rank = 0; lr = grow; }
    else if (grow < NR0 + NR1) { rank = 1; lr = grow - NR0; }
    else                       { rank = 2; lr = grow - NR0 - NR1; }
    const int* bel = (rank == 0) ? bel0 : (rank == 1 ? bel1 : bel2);
    int b = bel[lr];
    float v = g_xB[(size_t)grow * C + threadIdx.x];
    atomicAdd(&g_pooled[rank * NB * C + b * C + threadIdx.x], v);
}

__global__ void out_kernel(const float* __restrict__ Wr0, const float* __restrict__ br0,
                           const float* __restrict__ Wr1, const float* __restrict__ br1,
                           const float* __restrict__ Wr2, const float* __restrict__ br2,
                           float* __restrict__ out) {
    int b = blockIdx.x;
    int o = threadIdx.x;
    float acc = br0[o] + br1[o] + br2[o];
    const float* Wrs[3] = {Wr0, Wr1, Wr2};
    #pragma unroll
    for (int r = 0; r < 3; r++) {
        const float* Wr = Wrs[r];
        const float* p  = &g_pooled[r * NB * C + b * C];
        #pragma unroll 8
        for (int c = 0; c < C; c++) acc += p[c] * Wr[c * OUTC + o];
    }
    out[b * OUTC + o] = acc;
}

// ============================================================
extern "C" void kernel_launch(void* const* d_in, const int* in_sizes, int n_in,
                              void* d_out, int out_size) {
    const float* x0  = (const float*)d_in[0];
    const float* x1  = (const float*)d_in[1];
    const float* x2  = (const float*)d_in[2];
    const float* L0  = (const float*)d_in[3];
    const float* L1  = (const float*)d_in[4];
    const float* L2  = (const float*)d_in[5];
    const int*   bel0 = (const int*)d_in[6];
    const int*   bel1 = (const int*)d_in[7];
    const int*   bel2 = (const int*)d_in[8];
    const float* W0  = (const float*)d_in[9];
    const float* W1  = (const float*)d_in[10];
    const float* W2  = (const float*)d_in[11];
    const float* Wr0 = (const float*)d_in[12];
    const float* br0 = (const float*)d_in[13];
    const float* Wr1 = (const float*)d_in[14];
    const float* br1 = (const float*)d_in[15];
    const float* Wr2 = (const float*)d_in[16];
    const float* br2 = (const float*)d_in[17];

    dinv_kernel<<<NT, 128>>>(L0, L1, L2);

    for (int layer = 0; layer < 2; layer++) {
        xw_kernel<<<NT / 32, 256>>>(x0, x1, x2, W0, W1, W2, layer);
        gemm_mma<<<128, 256>>>(L0, L1, L2, layer);
    }

    zero_pooled_kernel<<<(3 * NB * C + 255) / 256, 256>>>();
    pool_kernel<<<NT, 64>>>(bel0, bel1, bel2);
    out_kernel<<<NB, OUTC>>>(Wr0, br0, Wr1, br1, Wr2, br2, (float*)d_out);
}

// round 4
// speedup vs baseline: 2.0786x; 1.1075x over previous
#include <cuda_runtime.h>
#include <cstdint>

#define NR0 4096
#define NR1 8192
#define NR2 4096
#define NT  16384     // NR0+NR1+NR2
#define C   64
#define OUTC 32
#define NB  64

// ---- scratch (device globals; no allocation allowed) ----
__device__ float    g_dinv[NT];
__device__ uint16_t g_zhi[C * NT];    // bf16 hi of z^T [C][NT] (K-major B operand)
__device__ uint16_t g_zlo[C * NT];    // bf16 lo
__device__ float    g_xA[NT * C];
__device__ float    g_xB[NT * C];
__device__ float    g_pooled[3 * NB * C];

// ============================================================
// helpers
// ============================================================
__device__ __forceinline__ uint32_t pack_bf16(float lo, float hi) {
    // result: [15:0] = bf16(lo), [31:16] = bf16(hi)
    uint32_t r;
    asm("cvt.rn.bf16x2.f32 %0, %1, %2;" : "=r"(r) : "f"(hi), "f"(lo));
    return r;
}
__device__ __forceinline__ uint16_t bf16_rn(float x) {
    uint16_t r;
    asm("cvt.rn.bf16.f32 %0, %1;" : "=h"(r) : "f"(x));
    return r;
}
__device__ __forceinline__ void mma_bf16(float* c, const uint32_t* a, const uint32_t* b) {
    asm volatile("mma.sync.aligned.m16n8k16.row.col.f32.bf16.bf16.f32 "
        "{%0,%1,%2,%3}, {%4,%5,%6,%7}, {%8,%9}, {%0,%1,%2,%3};"
        : "+f"(c[0]), "+f"(c[1]), "+f"(c[2]), "+f"(c[3])
        : "r"(a[0]), "r"(a[1]), "r"(a[2]), "r"(a[3]), "r"(b[0]), "r"(b[1]));
}

// ============================================================
// dinv[i] = rsqrt(rowsum |L_i|), 0 if rowsum == 0
// ============================================================
__global__ void dinv_kernel(const float* __restrict__ L0,
                            const float* __restrict__ L1,
                            const float* __restrict__ L2) {
    int grow = blockIdx.x;
    const float* L; int N; int lr;
    if (grow < NR0)             { L = L0; N = NR0; lr = grow; }
    else if (grow < NR0 + NR1)  { L = L1; N = NR1; lr = grow - NR0; }
    else                        { L = L2; N = NR2; lr = grow - NR0 - NR1; }

    const float4* row = (const float4*)(L + (size_t)lr * N);
    int n4 = N >> 2;
    float s = 0.f;
    for (int j = threadIdx.x; j < n4; j += blockDim.x) {
        float4 v = row[j];
        s += fabsf(v.x) + fabsf(v.y) + fabsf(v.z) + fabsf(v.w);
    }
    __shared__ float red[4];
    for (int o = 16; o > 0; o >>= 1) s += __shfl_down_sync(0xffffffffu, s, o);
    if ((threadIdx.x & 31) == 0) red[threadIdx.x >> 5] = s;
    __syncthreads();
    if (threadIdx.x == 0) {
        float d = red[0] + red[1] + red[2] + red[3];
        g_dinv[grow] = (d != 0.f) ? rsqrtf(d) : 0.f;
    }
}

// ============================================================
// z = dinv .* (x @ W[layer]); emit bf16 hi/lo transposed [C][NT]
// ============================================================
__global__ __launch_bounds__(256) void xw_kernel(
    const float* __restrict__ x0, const float* __restrict__ x1,
    const float* __restrict__ x2,
    const float* __restrict__ W0, const float* __restrict__ W1,
    const float* __restrict__ W2, int layer)
{
    __shared__ float Ws[C * C];
    __shared__ float xs[32 * C];
    __shared__ float zs[32][C + 1];

    int growBase = blockIdx.x * 32;
    const float* W; const float* xsrc;
    if (growBase < NR0) {
        W = W0;
        xsrc = layer ? (g_xA + (size_t)growBase * C) : (x0 + (size_t)growBase * C);
    } else if (growBase < NR0 + NR1) {
        W = W1;
        xsrc = layer ? (g_xA + (size_t)growBase * C) : (x1 + (size_t)(growBase - NR0) * C);
    } else {
        W = W2;
        xsrc = layer ? (g_xA + (size_t)growBase * C) : (x2 + (size_t)(growBase - NR0 - NR1) * C);
    }
    W += layer * C * C;

    int tid = threadIdx.x;
    for (int i = tid; i < C * C; i += 256) Ws[i] = W[i];
    for (int i = tid; i < 32 * C; i += 256) xs[i] = xsrc[i];
    __syncthreads();

    int c = tid & 63, rb = tid >> 6;
    #pragma unroll
    for (int rq = 0; rq < 8; rq++) {
        int r = rb * 8 + rq;
        float acc = 0.f;
        #pragma unroll
        for (int k = 0; k < C; k++) acc += xs[r * C + k] * Ws[k * C + c];
        zs[r][c] = acc * g_dinv[growBase + r];
    }
    __syncthreads();

    // transposed write, split into bf16 hi/lo, 8 contiguous rows per thread
    int c2 = tid >> 2, seg = tid & 3;
    size_t base = (size_t)c2 * NT + growBase + seg * 8;
    uint16_t hv[8], lv[8];
    #pragma unroll
    for (int j = 0; j < 8; j++) {
        float v = zs[seg * 8 + j][c2];
        uint16_t h = bf16_rn(v);
        hv[j] = h;
        lv[j] = bf16_rn(v - __uint_as_float((uint32_t)h << 16));
    }
    *(uint4*)&g_zhi[base] = *(uint4*)hv;
    *(uint4*)&g_zlo[base] = *(uint4*)lv;
}

// ============================================================
// mma.sync bf16x3 GEMM:  dst = relu(dinv .* (L @ z))
// BM=128, BN=64, BK=32, double-buffered smem (2 stages), 1 bar/chunk.
// 256 threads = 8 warps (4m x 2n), m32n32 per warp.
// ============================================================
#define SA 40   // smem row pitch in halves
#define SB 40
#define AH_OFF 0
#define AL_OFF (128 * SA)
#define BH_OFF (2 * 128 * SA)
#define BL_OFF (2 * 128 * SA + C * SB)
#define STAGE_HALVES (2 * 128 * SA + 2 * C * SB)
#define GEMM_SMEM (2 * STAGE_HALVES * 2)   // bytes

__global__ __launch_bounds__(256, 1) void gemm_mma(
    const float* __restrict__ L0, const float* __restrict__ L1,
    const float* __restrict__ L2, int layer)
{
    extern __shared__ __align__(16) uint16_t sm[];

    int bx = blockIdx.x;
    const float* L; int N, lrowBase, growBase;
    if (bx < 32)      { L = L0; N = NR0; lrowBase = bx * 128;        growBase = lrowBase; }
    else if (bx < 96) { L = L1; N = NR1; lrowBase = (bx - 32) * 128; growBase = NR0 + lrowBase; }
    else              { L = L2; N = NR2; lrowBase = (bx - 96) * 128; growBase = NR0 + NR1 + lrowBase; }
    int zOff = growBase - lrowBase;
    int nc = N / 32;
    float* dst = layer ? g_xB : g_xA;

    int tid = threadIdx.x;
    int wid = tid >> 5, lane = tid & 31;
    int g = lane >> 2, tg = lane & 3;
    int wm = wid >> 1, wn = wid & 1;

    // ---- loader setup ----
    // A: 128 rows x 32 k -> 1024 float4, 4 per thread
    const float* aPtr[4]; int aSts[4];
    #pragma unroll
    for (int q = 0; q < 4; q++) {
        int idx = q * 256 + tid;
        int aRow = idx >> 3, aK4 = idx & 7;
        aPtr[q] = L + (size_t)(lrowBase + aRow) * N + aK4 * 4;
        aSts[q] = aRow * SA + aK4 * 4;
    }
    // B: 64 rows x 32 halves -> 256 uint4 (hi) + 256 (lo), 1 each per thread
    int bRow = tid >> 2, bK8 = tid & 3;
    const uint16_t* bhPtr = g_zhi + (size_t)bRow * NT + zOff + bK8 * 8;
    const uint16_t* blPtr = g_zlo + (size_t)bRow * NT + zOff + bK8 * 8;
    int bSts = bRow * SB + bK8 * 8;

    float acc[2][4][4];
    #pragma unroll
    for (int mt = 0; mt < 2; mt++)
        #pragma unroll
        for (int nt = 0; nt < 4; nt++)
            #pragma unroll
            for (int i = 0; i < 4; i++) acc[mt][nt][i] = 0.f;

    float4 ra[4]; uint4 rbh, rbl;

    // ---- prologue: chunk 0 -> smem stage 0; chunk 1 -> regs ----
    #pragma unroll
    for (int q = 0; q < 4; q++) ra[q] = *(const float4*)(aPtr[q]);
    rbh = *(const uint4*)bhPtr;
    rbl = *(const uint4*)blPtr;

    {
        uint16_t* st = sm;   // stage 0
        #pragma unroll
        for (int q = 0; q < 4; q++) {
            float4 v = ra[q];
            uint32_t h0 = pack_bf16(v.x, v.y);
            uint32_t h1 = pack_bf16(v.z, v.w);
            float r0 = v.x - __uint_as_float(h0 << 16);
            float r1 = v.y - __uint_as_float(h0 & 0xFFFF0000u);
            float r2 = v.z - __uint_as_float(h1 << 16);
            float r3 = v.w - __uint_as_float(h1 & 0xFFFF0000u);
            *(uint2*)&st[AH_OFF + aSts[q]] = make_uint2(h0, h1);
            *(uint2*)&st[AL_OFF + aSts[q]] = make_uint2(pack_bf16(r0, r1), pack_bf16(r2, r3));
        }
        *(uint4*)&st[BH_OFF + bSts] = rbh;
        *(uint4*)&st[BL_OFF + bSts] = rbl;
    }
    if (nc > 1) {
        #pragma unroll
        for (int q = 0; q < 4; q++) ra[q] = *(const float4*)(aPtr[q] + 32);
        rbh = *(const uint4*)(bhPtr + 32);
        rbl = *(const uint4*)(blPtr + 32);
    }
    __syncthreads();

    // ---- mainloop: one barrier per chunk ----
    for (int cI = 0; cI < nc; cI++) {
        // store chunk cI+1 into the other stage (interleaves with MMA issue)
        if (cI + 1 < nc) {
            uint16_t* st = sm + ((cI + 1) & 1) * STAGE_HALVES;
            #pragma unroll
            for (int q = 0; q < 4; q++) {
                float4 v = ra[q];
                uint32_t h0 = pack_bf16(v.x, v.y);
                uint32_t h1 = pack_bf16(v.z, v.w);
                float r0 = v.x - __uint_as_float(h0 << 16);
                float r1 = v.y - __uint_as_float(h0 & 0xFFFF0000u);
                float r2 = v.z - __uint_as_float(h1 << 16);
                float r3 = v.w - __uint_as_float(h1 & 0xFFFF0000u);
                *(uint2*)&st[AH_OFF + aSts[q]] = make_uint2(h0, h1);
                *(uint2*)&st[AL_OFF + aSts[q]] = make_uint2(pack_bf16(r0, r1), pack_bf16(r2, r3));
            }
            *(uint4*)&st[BH_OFF + bSts] = rbh;
            *(uint4*)&st[BL_OFF + bSts] = rbl;
        }
        // prefetch chunk cI+2 into regs (lands during this chunk's compute)
        if (cI + 2 < nc) {
            int k0 = (cI + 2) * 32;
            #pragma unroll
            for (int q = 0; q < 4; q++) ra[q] = *(const float4*)(aPtr[q] + k0);
            rbh = *(const uint4*)(bhPtr + k0);
            rbl = *(const uint4*)(blPtr + k0);
        }

        // compute current stage
        const uint16_t* st = sm + (cI & 1) * STAGE_HALVES;
        #pragma unroll
        for (int ks = 0; ks < 2; ks++) {
            uint32_t ah[2][4], al[2][4];
            #pragma unroll
            for (int mt = 0; mt < 2; mt++) {
                int r0 = (wm * 32 + mt * 16 + g) * SA + ks * 16 + tg * 2;
                ah[mt][0] = *(const uint32_t*)&st[AH_OFF + r0];
                ah[mt][1] = *(const uint32_t*)&st[AH_OFF + r0 + 8 * SA];
                ah[mt][2] = *(const uint32_t*)&st[AH_OFF + r0 + 8];
                ah[mt][3] = *(const uint32_t*)&st[AH_OFF + r0 + 8 * SA + 8];
                al[mt][0] = *(const uint32_t*)&st[AL_OFF + r0];
                al[mt][1] = *(const uint32_t*)&st[AL_OFF + r0 + 8 * SA];
                al[mt][2] = *(const uint32_t*)&st[AL_OFF + r0 + 8];
                al[mt][3] = *(const uint32_t*)&st[AL_OFF + r0 + 8 * SA + 8];
            }
            uint32_t bh[4][2], bl[4][2];
            #pragma unroll
            for (int nt = 0; nt < 4; nt++) {
                int b0 = (wn * 32 + nt * 8 + g) * SB + ks * 16 + tg * 2;
                bh[nt][0] = *(const uint32_t*)&st[BH_OFF + b0];
                bh[nt][1] = *(const uint32_t*)&st[BH_OFF + b0 + 8];
                bl[nt][0] = *(const uint32_t*)&st[BL_OFF + b0];
                bl[nt][1] = *(const uint32_t*)&st[BL_OFF + b0 + 8];
            }
            #pragma unroll
            for (int mt = 0; mt < 2; mt++)
                #pragma unroll
                for (int nt = 0; nt < 4; nt++) {
                    mma_bf16(acc[mt][nt], ah[mt], bh[nt]);
                    mma_bf16(acc[mt][nt], ah[mt], bl[nt]);
                    mma_bf16(acc[mt][nt], al[mt], bh[nt]);
                }
        }
        __syncthreads();
    }

    // ---- epilogue: dinv row-scale + relu, write fp32 ----
    #pragma unroll
    for (int mt = 0; mt < 2; mt++) {
        int row0 = wm * 32 + mt * 16 + g;
        float dv0 = g_dinv[growBase + row0];
        float dv1 = g_dinv[growBase + row0 + 8];
        #pragma unroll
        for (int nt = 0; nt < 4; nt++) {
            int col = wn * 32 + nt * 8 + tg * 2;
            float* c = acc[mt][nt];
            float2 o0, o1;
            o0.x = fmaxf(c[0] * dv0, 0.f);
            o0.y = fmaxf(c[1] * dv0, 0.f);
            o1.x = fmaxf(c[2] * dv1, 0.f);
            o1.y = fmaxf(c[3] * dv1, 0.f);
            *(float2*)&dst[(size_t)(growBase + row0) * C + col]     = o0;
            *(float2*)&dst[(size_t)(growBase + row0 + 8) * C + col] = o1;
        }
    }
}

// ============================================================
// readout
// ============================================================
__global__ void zero_pooled_kernel() {
    int i = blockIdx.x * blockDim.x + threadIdx.x;
    if (i < 3 * NB * C) g_pooled[i] = 0.f;
}

__global__ void pool_kernel(const int* __restrict__ bel0,
                            const int* __restrict__ bel1,
                            const int* __restrict__ bel2) {
    int grow = blockIdx.x;
    int rank, lr;
    if (grow < NR0)            { rank = 0; lr = grow; }
    else if (grow < NR0 + NR1) { rank = 1; lr = grow - NR0; }
    else                       { rank = 2; lr = grow - NR0 - NR1; }
    const int* bel = (rank == 0) ? bel0 : (rank == 1 ? bel1 : bel2);
    int b = bel[lr];
    float v = g_xB[(size_t)grow * C + threadIdx.x];
    atomicAdd(&g_pooled[rank * NB * C + b * C + threadIdx.x], v);
}

__global__ void out_kernel(const float* __restrict__ Wr0, const float* __restrict__ br0,
                           const float* __restrict__ Wr1, const float* __restrict__ br1,
                           const float* __restrict__ Wr2, const float* __restrict__ br2,
                           float* __restrict__ out) {
    int b = blockIdx.x;
    int o = threadIdx.x;
    float acc = br0[o] + br1[o] + br2[o];
    const float* Wrs[3] = {Wr0, Wr1, Wr2};
    #pragma unroll
    for (int r = 0; r < 3; r++) {
        const float* Wr = Wrs[r];
        const float* p  = &g_pooled[r * NB * C + b * C];
        #pragma unroll 8
        for (int c = 0; c < C; c++) acc += p[c] * Wr[c * OUTC + o];
    }
    out[b * OUTC + o] = acc;
}

// ============================================================
extern "C" void kernel_launch(void* const* d_in, const int* in_sizes, int n_in,
                              void* d_out, int out_size) {
    const float* x0  = (const float*)d_in[0];
    const float* x1  = (const float*)d_in[1];
    const float* x2  = (const float*)d_in[2];
    const float* L0  = (const float*)d_in[3];
    const float* L1  = (const float*)d_in[4];
    const float* L2  = (const float*)d_in[5];
    const int*   bel0 = (const int*)d_in[6];
    const int*   bel1 = (const int*)d_in[7];
    const int*   bel2 = (const int*)d_in[8];
    const float* W0  = (const float*)d_in[9];
    const float* W1  = (const float*)d_in[10];
    const float* W2  = (const float*)d_in[11];
    const float* Wr0 = (const float*)d_in[12];
    const float* br0 = (const float*)d_in[13];
    const float* Wr1 = (const float*)d_in[14];
    const float* br1 = (const float*)d_in[15];
    const float* Wr2 = (const float*)d_in[16];
    const float* br2 = (const float*)d_in[17];

    cudaFuncSetAttribute(gemm_mma, cudaFuncAttributeMaxDynamicSharedMemorySize, GEMM_SMEM);

    dinv_kernel<<<NT, 128>>>(L0, L1, L2);

    for (int layer = 0; layer < 2; layer++) {
        xw_kernel<<<NT / 32, 256>>>(x0, x1, x2, W0, W1, W2, layer);
        gemm_mma<<<128, 256, GEMM_SMEM>>>(L0, L1, L2, layer);
    }

    zero_pooled_kernel<<<(3 * NB * C + 255) / 256, 256>>>();
    pool_kernel<<<NT, 64>>>(bel0, bel1, bel2);
    out_kernel<<<NB, OUTC>>>(Wr0, br0, Wr1, br1, Wr2, br2, (float*)d_out);
}